// round 13
// baseline (speedup 1.0000x reference)
#include <cuda_runtime.h>
#include <cuda_fp16.h>
#include <math.h>
#include <stdint.h>

// Problem constants
#define T_TOK   2048
#define D_MODEL 1024
#define N_EXP   8
#define HIDDEN  4096
#define TOPK    2
#define CAP     2048

// ---------------- scratch (device globals; no dynamic allocation) ----------
__device__ int    g_counts[N_EXP];
__device__ int    g_tok_expert[T_TOK * TOPK];
__device__ int    g_tok_slot[T_TOK * TOPK];
__device__ float  g_tok_weight[T_TOK * TOPK];
__device__ __align__(16) __half g_xg[(size_t)N_EXP * CAP * D_MODEL];  // 32 MB
__device__ __align__(16) __half g_h [(size_t)N_EXP * CAP * HIDDEN];   // 128 MB
__device__ __align__(16) float  g_eo[(size_t)N_EXP * CAP * D_MODEL];  // 64 MB

// ---------------- kernel 0: zero counters (prewarm only) -------------------
__global__ void zero_counts_kernel() {
    if (threadIdx.x < N_EXP) g_counts[threadIdx.x] = 0;
}

__device__ __forceinline__ uint32_t pack_h2(float x, float y) {
    __half2 h = __floats2half2_rn(x, y);
    return *(uint32_t*)&h;
}
__device__ __forceinline__ uint32_t smem_u32(const void* p) {
    uint32_t a;
    asm("{ .reg .u64 t; cvta.to.shared.u64 t, %1; cvt.u32.u64 %0, t; }" : "=r"(a) : "l"(p));
    return a;
}
__device__ __forceinline__ void ldm_x4(uint32_t* r, uint32_t addr) {
    asm volatile("ldmatrix.sync.aligned.m8n8.x4.shared.b16 {%0,%1,%2,%3}, [%4];"
        : "=r"(r[0]), "=r"(r[1]), "=r"(r[2]), "=r"(r[3]) : "r"(addr));
}

// ---------------- kernel 1: routing, 8 tokens/block (1 warp/token) ---------
// Block-aggregated counts: smem atomics give local slots, ONE global atomic
// per (block, expert). Slot permutation vs before is output-invariant.
// No dynamically-indexed local arrays anywhere (lmem-pool guard).
__global__ __launch_bounds__(256)
void routing_kernel(const float* __restrict__ x,
                    const float* __restrict__ gate_w) {
    const int tid = threadIdx.x, w = tid >> 5, lane = tid & 31;
    const int t = blockIdx.x * 8 + w;

    // cache token row in regs: chunk i = floats [i*128 + lane*4 .. +3]
    const float4* xr = (const float4*)(x + (size_t)t * D_MODEL);
    float4 ra0 = xr[lane];       float4 ra1 = xr[32 + lane];
    float4 ra2 = xr[64 + lane];  float4 ra3 = xr[96 + lane];
    float4 ra4 = xr[128 + lane]; float4 ra5 = xr[160 + lane];
    float4 ra6 = xr[192 + lane]; float4 ra7 = xr[224 + lane];

    __shared__ float slog[8][N_EXP];
    __shared__ int   scnt[N_EXP];
    __shared__ int   sbase[N_EXP];
    __shared__ int   se[8][2];
    __shared__ int   sslot[8][2];

    if (tid < N_EXP) scnt[tid] = 0;

    #pragma unroll
    for (int e = 0; e < N_EXP; e++) {
        const float4* gr = (const float4*)(gate_w + (size_t)e * D_MODEL);
        float4 g0 = gr[lane],       g1 = gr[32 + lane];
        float4 g2 = gr[64 + lane],  g3 = gr[96 + lane];
        float4 g4 = gr[128 + lane], g5 = gr[160 + lane];
        float4 g6 = gr[192 + lane], g7 = gr[224 + lane];
        float s = ra0.x*g0.x + ra0.y*g0.y + ra0.z*g0.z + ra0.w*g0.w
                + ra1.x*g1.x + ra1.y*g1.y + ra1.z*g1.z + ra1.w*g1.w
                + ra2.x*g2.x + ra2.y*g2.y + ra2.z*g2.z + ra2.w*g2.w
                + ra3.x*g3.x + ra3.y*g3.y + ra3.z*g3.z + ra3.w*g3.w
                + ra4.x*g4.x + ra4.y*g4.y + ra4.z*g4.z + ra4.w*g4.w
                + ra5.x*g5.x + ra5.y*g5.y + ra5.z*g5.z + ra5.w*g5.w
                + ra6.x*g6.x + ra6.y*g6.y + ra6.z*g6.z + ra6.w*g6.w
                + ra7.x*g7.x + ra7.y*g7.y + ra7.z*g7.z + ra7.w*g7.w;
        #pragma unroll
        for (int off = 16; off; off >>= 1) s += __shfl_xor_sync(0xffffffffu, s, off);
        if (lane == 0) slog[w][e] = s;
    }
    __syncthreads();

    if (lane == 0) {
        float mx = slog[w][0];
        #pragma unroll
        for (int i = 1; i < N_EXP; i++) mx = fmaxf(mx, slog[w][i]);
        float denom = 0.f;
        #pragma unroll
        for (int i = 0; i < N_EXP; i++) denom += expf(slog[w][i] - mx);
        // top-2 scan; strict '>' keeps lower index on ties (matches jax top_k)
        float v0 = -3.4e38f, v1 = -3.4e38f;
        int   i0 = 0,        i1 = 0;
        #pragma unroll
        for (int i = 0; i < N_EXP; i++) {
            float v = slog[w][i];
            if (v > v0)      { v1 = v0; i1 = i0; v0 = v; i0 = i; }
            else if (v > v1) { v1 = v;  i1 = i; }
        }
        float p0 = expf(v0 - mx) / denom;
        float p1 = expf(v1 - mx) / denom;
        float inv = 1.f / (p0 + p1);
        p0 *= inv; p1 *= inv;
        int l0 = atomicAdd(&scnt[i0], 1);
        int l1 = atomicAdd(&scnt[i1], 1);
        se[w][0] = i0; sslot[w][0] = l0;
        se[w][1] = i1; sslot[w][1] = l1;
        g_tok_weight[t * 2 + 0] = p0;
        g_tok_weight[t * 2 + 1] = p1;
    }
    __syncthreads();

    if (tid < N_EXP && scnt[tid] > 0) sbase[tid] = atomicAdd(&g_counts[tid], scnt[tid]);
    __syncthreads();

    if (lane == 0) {
        int e0 = se[w][0], e1 = se[w][1];
        int s0 = sbase[e0] + sslot[w][0];
        int s1 = sbase[e1] + sslot[w][1];
        sslot[w][0] = s0; sslot[w][1] = s1;
        g_tok_expert[t * 2 + 0] = e0;  g_tok_slot[t * 2 + 0] = s0;
        g_tok_expert[t * 2 + 1] = e1;  g_tok_slot[t * 2 + 1] = s1;
    }
    __syncwarp();

    // gather: pack row to fp16, write both expert buffers
    uint2 h0 = make_uint2(pack_h2(ra0.x, ra0.y), pack_h2(ra0.z, ra0.w));
    uint2 h1 = make_uint2(pack_h2(ra1.x, ra1.y), pack_h2(ra1.z, ra1.w));
    uint2 h2 = make_uint2(pack_h2(ra2.x, ra2.y), pack_h2(ra2.z, ra2.w));
    uint2 h3 = make_uint2(pack_h2(ra3.x, ra3.y), pack_h2(ra3.z, ra3.w));
    uint2 h4 = make_uint2(pack_h2(ra4.x, ra4.y), pack_h2(ra4.z, ra4.w));
    uint2 h5 = make_uint2(pack_h2(ra5.x, ra5.y), pack_h2(ra5.z, ra5.w));
    uint2 h6 = make_uint2(pack_h2(ra6.x, ra6.y), pack_h2(ra6.z, ra6.w));
    uint2 h7 = make_uint2(pack_h2(ra7.x, ra7.y), pack_h2(ra7.z, ra7.w));
    #pragma unroll
    for (int c = 0; c < 2; c++) {
        int ec = __shfl_sync(0xffffffffu, se[w][c], 0);        // broadcast-safe
        int sc = __shfl_sync(0xffffffffu, sslot[w][c], 0);
        uint2* dst = (uint2*)(g_xg + ((size_t)ec * CAP + sc) * D_MODEL);
        dst[lane] = h0;        dst[32 + lane] = h1;
        dst[64 + lane] = h2;   dst[96 + lane] = h3;
        dst[128 + lane] = h4;  dst[160 + lane] = h5;
        dst[192 + lane] = h6;  dst[224 + lane] = h7;
    }
}

// ---------------- fp16 tensor-core grouped NT GEMM -------------------------
// Identical core to R12 (333.8us) + 64-row warp-band skip for ragged tiles.
#define BM 128
#define BN 128
#define BK 32
#define BKH 40   // half stride (80 B)

__device__ __forceinline__ void mma_f16(float* c, const uint32_t* a, const uint32_t* b) {
    asm volatile(
        "mma.sync.aligned.m16n8k16.row.col.f32.f16.f16.f32 "
        "{%0,%1,%2,%3}, {%4,%5,%6,%7}, {%8,%9}, {%0,%1,%2,%3};"
        : "+f"(c[0]), "+f"(c[1]), "+f"(c[2]), "+f"(c[3])
        : "r"(a[0]), "r"(a[1]), "r"(a[2]), "r"(a[3]), "r"(b[0]), "r"(b[1]));
}

template<bool RELU, typename OutT>
__global__ __launch_bounds__(256)
void gemm_tc_kernel(const __half* __restrict__ Ab, const float* __restrict__ Bb,
                    const float* __restrict__ biasb, OutT* __restrict__ Cb,
                    int K, int N) {
    const int e  = blockIdx.z;
    const int M  = g_counts[e];
    const int m0 = blockIdx.x * BM;          // m fastest: wave shares B tile in L2
    if (m0 >= M) return;
    const int n0 = blockIdx.y * BN;

    const __half* A    = Ab    + (size_t)e * CAP * K;
    const float*  B    = Bb    + (size_t)e * N   * K;
    const float*  bias = biasb + (size_t)e * N;
    OutT*         C    = Cb    + (size_t)e * CAP * N;

    __shared__ __align__(16) __half As[2][BM][BKH];
    __shared__ __align__(16) __half Bs[2][BN][BKH];

    const int tid  = threadIdx.x;
    const int warp = tid >> 5, lane = tid & 31;
    const int wm   = warp >> 2;
    const int wn   = warp & 3;
    const int grp  = lane >> 2;
    const int tig  = lane & 3;

    // ragged-tile skip: this warp's 64-row band entirely beyond M?
    const bool wact = (wm * 64) < (M - m0);

    const int arow = tid >> 3;
    const int aj   = (tid & 7) * 4;    // halves
    const int sk   = (tid & 7) * 4;    // floats

    const uint32_t sA = smem_u32(&As[0][0][0]);
    const uint32_t sB = smem_u32(&Bs[0][0][0]);
    const uint32_t ABUF = BM * BKH * 2, BBUF = BN * BKH * 2;
    const uint32_t aLane = (uint32_t)((wm * 64 + (lane & 15)) * (BKH * 2) + (lane >> 4) * 16);
    const uint32_t bLane = (uint32_t)((wn * 32 + ((lane >> 3) & 2) * 4 + (lane & 7)) * (BKH * 2)
                                      + ((lane >> 3) & 1) * 16);

    float acc[4][4][4];
    #pragma unroll
    for (int mi = 0; mi < 4; mi++)
        #pragma unroll
        for (int ni = 0; ni < 4; ni++)
            #pragma unroll
            for (int r = 0; r < 4; r++) acc[mi][ni][r] = 0.f;

    uint2  qa[4];
    float4 rb[4];
    const int T = K / BK;

    #pragma unroll
    for (int r = 0; r < 4; r++) {
        int gm = m0 + arow + r * 32;
        qa[r] = (gm < M) ? *(const uint2*)&A[(size_t)gm * K + aj] : make_uint2(0u, 0u);
        rb[r] = *(const float4*)&B[(size_t)(n0 + arow + r * 32) * K + sk];
    }
    #pragma unroll
    for (int r = 0; r < 4; r++) {
        *(uint2*)&As[0][arow + r * 32][aj] = qa[r];
        *(uint2*)&Bs[0][arow + r * 32][sk] =
            make_uint2(pack_h2(rb[r].x, rb[r].y), pack_h2(rb[r].z, rb[r].w));
    }
    __syncthreads();

    for (int t = 0; t < T; t++) {
        const int cur = t & 1, nxt = cur ^ 1;
        const bool more = (t + 1 < T);

        if (more) {
            const int kb = (t + 1) * BK;
            #pragma unroll
            for (int r = 0; r < 4; r++) {
                int gm = m0 + arow + r * 32;
                qa[r] = (gm < M) ? *(const uint2*)&A[(size_t)gm * K + kb + aj] : make_uint2(0u, 0u);
                rb[r] = *(const float4*)&B[(size_t)(n0 + arow + r * 32) * K + kb + sk];
            }
        }

        if (wact) {
            const uint32_t aB = sA + (uint32_t)cur * ABUF + aLane;
            const uint32_t bB = sB + (uint32_t)cur * BBUF + bLane;
            #pragma unroll
            for (int kk = 0; kk < BK; kk += 16) {
                const uint32_t ko = (uint32_t)kk * 2;
                uint32_t af[4][4], bq[2][4];
                #pragma unroll
                for (int mi = 0; mi < 4; mi++)
                    ldm_x4(af[mi], aB + ko + (uint32_t)(mi * 16 * BKH * 2));
                #pragma unroll
                for (int p = 0; p < 2; p++)
                    ldm_x4(bq[p], bB + ko + (uint32_t)(p * 16 * BKH * 2));
                #pragma unroll
                for (int mi = 0; mi < 4; mi++) {
                    #pragma unroll
                    for (int p = 0; p < 2; p++) {
                        mma_f16(acc[mi][2 * p + 0], af[mi], &bq[p][0]);
                        mma_f16(acc[mi][2 * p + 1], af[mi], &bq[p][2]);
                    }
                }
            }
        }

        if (more) {
            #pragma unroll
            for (int r = 0; r < 4; r++) {
                *(uint2*)&As[nxt][arow + r * 32][aj] = qa[r];
                *(uint2*)&Bs[nxt][arow + r * 32][sk] =
                    make_uint2(pack_h2(rb[r].x, rb[r].y), pack_h2(rb[r].z, rb[r].w));
            }
            __syncthreads();
        }
    }

    if (wact) {
        #pragma unroll
        for (int mi = 0; mi < 4; mi++) {
            int r0 = m0 + wm * 64 + mi * 16 + grp;
            int r1 = r0 + 8;
            #pragma unroll
            for (int ni = 0; ni < 4; ni++) {
                int col = n0 + wn * 32 + ni * 8 + tig * 2;
                float2 bv = *(const float2*)&bias[col];
                if (r0 < M) {
                    float ox = acc[mi][ni][0] + bv.x, oy = acc[mi][ni][1] + bv.y;
                    if (RELU) { ox = fmaxf(ox, 0.f); oy = fmaxf(oy, 0.f); }
                    if constexpr (sizeof(OutT) == 2) {
                        *(uint32_t*)&C[(size_t)r0 * N + col] = pack_h2(ox, oy);
                    } else {
                        *(float2*)&C[(size_t)r0 * N + col] = make_float2(ox, oy);
                    }
                }
                if (r1 < M) {
                    float ox = acc[mi][ni][2] + bv.x, oy = acc[mi][ni][3] + bv.y;
                    if (RELU) { ox = fmaxf(ox, 0.f); oy = fmaxf(oy, 0.f); }
                    if constexpr (sizeof(OutT) == 2) {
                        *(uint32_t*)&C[(size_t)r1 * N + col] = pack_h2(ox, oy);
                    } else {
                        *(float2*)&C[(size_t)r1 * N + col] = make_float2(ox, oy);
                    }
                }
            }
        }
    }
}

// ---------------- deterministic weighted combine + counter reset -----------
__global__ void combine_kernel(float* __restrict__ out) {
    int t = blockIdx.x;
    // reset counters for the NEXT graph replay (combine is the last kernel;
    // g_counts is no longer needed within this launch)
    if (t == 0 && threadIdx.x < N_EXP) g_counts[threadIdx.x] = 0;

    int e0 = g_tok_expert[t * 2 + 0], e1 = g_tok_expert[t * 2 + 1];
    int s0 = g_tok_slot[t * 2 + 0],   s1 = g_tok_slot[t * 2 + 1];
    float w0 = g_tok_weight[t * 2 + 0], w1 = g_tok_weight[t * 2 + 1];
    const float4* r0 = (const float4*)(g_eo + ((size_t)e0 * CAP + s0) * D_MODEL);
    const float4* r1 = (const float4*)(g_eo + ((size_t)e1 * CAP + s1) * D_MODEL);
    float4* o = (float4*)(out + (size_t)t * D_MODEL);
    int i = threadIdx.x;
    float4 a = r0[i], b = r1[i];
    float4 v;
    v.x = w0 * a.x + w1 * b.x;
    v.y = w0 * a.y + w1 * b.y;
    v.z = w0 * a.z + w1 * b.z;
    v.w = w0 * a.w + w1 * b.w;
    o[i] = v;
}

// ---------------- device addresses + prewarm --------------------------------
static __half* p_xg = nullptr;
static __half* p_h  = nullptr;
static float*  p_eo = nullptr;

static struct Prewarm {
    Prewarm() {
        (void)cudaGetSymbolAddress((void**)&p_xg, g_xg);
        (void)cudaGetSymbolAddress((void**)&p_h,  g_h);
        (void)cudaGetSymbolAddress((void**)&p_eo, g_eo);
        // prewarm every kernel pre-baseline (module load, lazy driver pools).
        zero_counts_kernel<<<1, 32>>>();
        routing_kernel<<<1, 256>>>(p_eo, p_eo);          // scratch in/out
        dim3 g1(1, 1, 1);
        gemm_tc_kernel<true,  __half><<<g1, 256>>>(p_xg, p_eo, p_eo, p_h, D_MODEL, HIDDEN);
        gemm_tc_kernel<false, float ><<<g1, 256>>>(p_h, p_eo, p_eo, p_eo, HIDDEN, D_MODEL);
        combine_kernel<<<1, 256>>>(p_eo);
        zero_counts_kernel<<<1, 32>>>();                 // counts = 0 for launch #1
        (void)cudaDeviceSynchronize();
    }
} s_prewarm;

// ---------------- launch ----------------------------------------------------
extern "C" void kernel_launch(void* const* d_in, const int* in_sizes, int n_in,
                              void* d_out, int out_size) {
    const float* x      = (const float*)d_in[0];
    const float* gate_w = (const float*)d_in[1];
    const float* w1     = (const float*)d_in[2];
    const float* b1     = (const float*)d_in[3];
    const float* w2     = (const float*)d_in[4];
    const float* b2     = (const float*)d_in[5];
    float* out          = (float*)d_out;

    // counts start at 0 (prewarm for the first call; combine's tail resets
    // them at the end of every launch/replay)
    routing_kernel<<<T_TOK / 8, 256>>>(x, gate_w);

    // fc1 + relu: [count x 1024](fp16) @ [4096 x 1024]^T -> [count x 4096](fp16)
    dim3 g1(CAP / BM, HIDDEN / BN, N_EXP);
    gemm_tc_kernel<true, __half><<<g1, 256>>>(p_xg, w1, b1, p_h, D_MODEL, HIDDEN);

    // fc2: [count x 4096](fp16) @ [1024 x 4096]^T -> [count x 1024](fp32)
    dim3 g2(CAP / BM, D_MODEL / BN, N_EXP);
    gemm_tc_kernel<false, float><<<g2, 256>>>(p_h, w2, b2, p_eo, HIDDEN, D_MODEL);

    combine_kernel<<<T_TOK, 256>>>(out);
}